// round 7
// baseline (speedup 1.0000x reference)
#include <cuda_runtime.h>
#include <math.h>

// Segment sums + completion counter, zero-initialized at module load; the
// last-finishing warp re-zeroes them each run so graph replays are
// deterministic. Sized for B up to 8192.
__device__ float g_pos_sum[8192];
__device__ float g_neg_sum[8192];
__device__ unsigned int g_done_ctr;

// ---------------------------------------------------------------------------
// Single kernel. Streaming path identical to the 119.3us version: warp-per-row
// exp(cosine), lane0 atomicAdd into per-item segment sums, warps retire
// immediately (no block barrier, no grid handshake on the common path).
// Completion is tracked per-WARP: lane0 fences + bumps a row counter after its
// segment atomic. The warp that observes the final count finalizes alone:
// reads the 2*B segment sums (32KB, L2-hot), computes the per-item losses,
// warp-reduces, writes out[0], and resets the scratch.
// ---------------------------------------------------------------------------
__global__ void __launch_bounds__(256) contrastive_kernel(
    const float* __restrict__ q_pos, const float* __restrict__ i_pos,
    const float* __restrict__ q_neg, const float* __restrict__ i_neg,
    float* __restrict__ out, int pos_rows, int total_rows, int n_items)
{
    const int w = (blockIdx.x * blockDim.x + threadIdx.x) >> 5;
    const int lane = threadIdx.x & 31;
    if (w >= total_rows) return;

    const float4* __restrict__ a4;
    const float4* __restrict__ b4;
    float* __restrict__ dst;
    if (w < pos_rows) {
        a4 = reinterpret_cast<const float4*>(q_pos) + (size_t)w * 256;
        b4 = reinterpret_cast<const float4*>(i_pos) + (size_t)w * 256;
        dst = &g_pos_sum[w >> 1];                  // 2 pos rows per item
    } else {
        const int r = w - pos_rows;
        a4 = reinterpret_cast<const float4*>(q_neg) + (size_t)r * 256;
        b4 = reinterpret_cast<const float4*>(i_neg) + (size_t)r * 256;
        dst = &g_neg_sum[r / 23];                  // 23 neg rows per item
    }

    float dot = 0.0f, na2 = 0.0f, nb2 = 0.0f;
#pragma unroll
    for (int i = 0; i < 8; i++) {
        float4 va = __ldg(a4 + lane + i * 32);
        float4 vb = __ldg(b4 + lane + i * 32);
        dot = fmaf(va.x, vb.x, dot); na2 = fmaf(va.x, va.x, na2); nb2 = fmaf(vb.x, vb.x, nb2);
        dot = fmaf(va.y, vb.y, dot); na2 = fmaf(va.y, va.y, na2); nb2 = fmaf(vb.y, vb.y, nb2);
        dot = fmaf(va.z, vb.z, dot); na2 = fmaf(va.z, va.z, na2); nb2 = fmaf(vb.z, vb.z, nb2);
        dot = fmaf(va.w, vb.w, dot); na2 = fmaf(va.w, va.w, na2); nb2 = fmaf(vb.w, vb.w, nb2);
    }
#pragma unroll
    for (int off = 16; off > 0; off >>= 1) {
        dot += __shfl_xor_sync(0xffffffffu, dot, off);
        na2 += __shfl_xor_sync(0xffffffffu, na2, off);
        nb2 += __shfl_xor_sync(0xffffffffu, nb2, off);
    }

    // Per-warp completion: segment atomic, release fence, counter bump.
    int is_last = 0;
    if (lane == 0) {
        float denom = fmaxf(sqrtf(na2) * sqrtf(nb2), 1e-8f);
        atomicAdd(dst, expf(dot / denom));
        __threadfence();   // order segment atomic before the counter bump
        unsigned int prev = atomicAdd(&g_done_ctr, 1u);
        is_last = (prev == (unsigned int)total_rows - 1u);
    }
    is_last = __shfl_sync(0xffffffffu, is_last, 0);
    if (!is_last) return;

    // ---- Finalize: exactly one warp reaches here, after ALL row atomics ----
    __threadfence();       // acquire side
    const float4* p4 = reinterpret_cast<const float4*>(g_pos_sum);
    const float4* n4 = reinterpret_cast<const float4*>(g_neg_sum);
    float4* p4w = reinterpret_cast<float4*>(g_pos_sum);
    float4* n4w = reinterpret_cast<float4*>(g_neg_sum);
    const float4 z4 = make_float4(0.f, 0.f, 0.f, 0.f);

    float acc = 0.0f;
    const int nq = n_items >> 2;   // n_items divisible by 4 (B=4096)
    for (int i = lane; i < nq; i += 32) {
        float4 p = __ldcg(p4 + i);
        float4 n = __ldcg(n4 + i);
        acc += (n.x - p.x) / (p.x + n.x + 0.001f);
        acc += (n.y - p.y) / (p.y + n.y + 0.001f);
        acc += (n.z - p.z) / (p.z + n.z + 0.001f);
        acc += (n.w - p.w) / (p.w + n.w + 0.001f);
        p4w[i] = z4;               // restore scratch for next replay
        n4w[i] = z4;
    }
#pragma unroll
    for (int off = 16; off > 0; off >>= 1)
        acc += __shfl_xor_sync(0xffffffffu, acc, off);
    if (lane == 0) {
        out[0] = acc;              // single writer: no init/atomic needed
        g_done_ctr = 0;            // reset for next replay
    }
}

// ---------------------------------------------------------------------------
// Inputs (metadata order):
//   0: question_embeddings_pos  [2B, 1024] f32
//   1: question_embeddings_neg  [23B, 1024] f32
//   2: pos_image_embeddings     [2B, 1024] f32
//   3: neg_image_embeddings     [23B, 1024] f32
//   4: batch_size (int scalar)
// Output: f32 scalar.
// ---------------------------------------------------------------------------
extern "C" void kernel_launch(void* const* d_in, const int* in_sizes, int n_in,
                              void* d_out, int out_size) {
    const float* q_pos = (const float*)d_in[0];
    const float* q_neg = (const float*)d_in[1];
    const float* i_pos = (const float*)d_in[2];
    const float* i_neg = (const float*)d_in[3];
    float* out = (float*)d_out;

    const int D = 1024;
    const int B = in_sizes[0] / (2 * D);
    const int pos_rows = 2 * B;
    const int total_rows = 25 * B;

    const int WPB = 8;  // 256 threads / block
    contrastive_kernel<<<(total_rows + WPB - 1) / WPB, WPB * 32>>>(
        q_pos, i_pos, q_neg, i_neg, out, pos_rows, total_rows, B);
}

// round 8
// speedup vs baseline: 1.9483x; 1.9483x over previous
#include <cuda_runtime.h>
#include <math.h>

// Segment sums + grid completion counter, zero-initialized at module load;
// the grid-last warp re-zeroes them each run so graph replays are
// deterministic. Sized for B up to 8192.
__device__ float g_pos_sum[8192];
__device__ float g_neg_sum[8192];
__device__ unsigned int g_done_ctr;

// ---------------------------------------------------------------------------
// Single kernel, hierarchical completion (no gpu-scope fences, no hot atomic):
//   per warp : membar.cta + smem counter bump (SM-local, cheap)
//   per block: block-last warp does ONE atom.acq_rel.gpu on a global counter
//              (12,800 ops total -> ~113/us at one address, far below the
//               ~1.17 op/cyc single-address L2 atomic capacity)
//   grid-last: one warp finalizes (32KB L2 reads + warp reduce + out[0]),
//              then resets scratch for the next graph replay.
// Streaming hot path is identical to the 119.3us two-kernel version.
// ---------------------------------------------------------------------------
__global__ void __launch_bounds__(256) contrastive_kernel(
    const float* __restrict__ q_pos, const float* __restrict__ i_pos,
    const float* __restrict__ q_neg, const float* __restrict__ i_neg,
    float* __restrict__ out, int pos_rows, int total_rows, int n_items)
{
    __shared__ unsigned int s_ctr;
    if (threadIdx.x == 0) s_ctr = 0;
    __syncthreads();   // at kernel START: warps are aligned here anyway

    const int w = (blockIdx.x * blockDim.x + threadIdx.x) >> 5;
    const int lane = threadIdx.x & 31;
    const unsigned int nwarps = blockDim.x >> 5;

    // ---- Phase 1: streaming row cosine (predicated, no trailing barrier) ----
    if (w < total_rows) {
        const float4* __restrict__ a4;
        const float4* __restrict__ b4;
        float* __restrict__ dst;
        if (w < pos_rows) {
            a4 = reinterpret_cast<const float4*>(q_pos) + (size_t)w * 256;
            b4 = reinterpret_cast<const float4*>(i_pos) + (size_t)w * 256;
            dst = &g_pos_sum[w >> 1];                  // 2 pos rows per item
        } else {
            const int r = w - pos_rows;
            a4 = reinterpret_cast<const float4*>(q_neg) + (size_t)r * 256;
            b4 = reinterpret_cast<const float4*>(i_neg) + (size_t)r * 256;
            dst = &g_neg_sum[r / 23];                  // 23 neg rows per item
        }

        float dot = 0.0f, na2 = 0.0f, nb2 = 0.0f;
#pragma unroll
        for (int i = 0; i < 8; i++) {
            float4 va = __ldg(a4 + lane + i * 32);
            float4 vb = __ldg(b4 + lane + i * 32);
            dot = fmaf(va.x, vb.x, dot); na2 = fmaf(va.x, va.x, na2); nb2 = fmaf(vb.x, vb.x, nb2);
            dot = fmaf(va.y, vb.y, dot); na2 = fmaf(va.y, va.y, na2); nb2 = fmaf(vb.y, vb.y, nb2);
            dot = fmaf(va.z, vb.z, dot); na2 = fmaf(va.z, va.z, na2); nb2 = fmaf(vb.z, vb.z, nb2);
            dot = fmaf(va.w, vb.w, dot); na2 = fmaf(va.w, va.w, na2); nb2 = fmaf(vb.w, vb.w, nb2);
        }
#pragma unroll
        for (int off = 16; off > 0; off >>= 1) {
            dot += __shfl_xor_sync(0xffffffffu, dot, off);
            na2 += __shfl_xor_sync(0xffffffffu, na2, off);
            nb2 += __shfl_xor_sync(0xffffffffu, nb2, off);
        }
        if (lane == 0) {
            float denom = fmaxf(sqrtf(na2) * sqrtf(nb2), 1e-8f);
            atomicAdd(dst, expf(dot / denom));
        }
    }

    // ---- Per-warp completion: cta-scope fence + SHARED-memory counter ----
    unsigned int bprev = 0;
    if (lane == 0) {
        __threadfence_block();          // MEMBAR.CTA: no CCTL.IVALL, SM-local
        bprev = atomicAdd(&s_ctr, 1u);  // ATOMS: no L2 traffic
    }
    bprev = __shfl_sync(0xffffffffu, bprev, 0);
    if (bprev != nwarps - 1) return;    // non-last warps retire immediately

    // ---- Block-last warp: one scoped global bump (no MEMBAR.GPU) ----
    unsigned int gprev = 0;
    if (lane == 0) {
        __threadfence_block();          // acquire block peers' seg atomics
        asm volatile("atom.acq_rel.gpu.global.add.u32 %0, [%1], %2;"
                     : "=r"(gprev)
                     : "l"(&g_done_ctr), "r"(1u)
                     : "memory");
    }
    gprev = __shfl_sync(0xffffffffu, gprev, 0);
    if (gprev != gridDim.x - 1) return;

    // ---- Grid-last warp: finalize (all producers' atomics now visible) ----
    const float4* p4 = reinterpret_cast<const float4*>(g_pos_sum);
    const float4* n4 = reinterpret_cast<const float4*>(g_neg_sum);
    float4* p4w = reinterpret_cast<float4*>(g_pos_sum);
    float4* n4w = reinterpret_cast<float4*>(g_neg_sum);
    const float4 z4 = make_float4(0.f, 0.f, 0.f, 0.f);

    float acc = 0.0f;
    const int nq = n_items >> 2;        // n_items divisible by 4 (B=4096)
    for (int i = lane; i < nq; i += 32) {
        float4 p = __ldcg(p4 + i);      // L2 reads (atomics live at L2)
        float4 n = __ldcg(n4 + i);
        acc += (n.x - p.x) / (p.x + n.x + 0.001f);
        acc += (n.y - p.y) / (p.y + n.y + 0.001f);
        acc += (n.z - p.z) / (p.z + n.z + 0.001f);
        acc += (n.w - p.w) / (p.w + n.w + 0.001f);
        p4w[i] = z4;                    // restore scratch for next replay
        n4w[i] = z4;
    }
#pragma unroll
    for (int off = 16; off > 0; off >>= 1)
        acc += __shfl_xor_sync(0xffffffffu, acc, off);
    if (lane == 0) {
        out[0] = acc;                   // single writer
        g_done_ctr = 0;                 // reset for next replay
    }
}

// ---------------------------------------------------------------------------
// Inputs (metadata order):
//   0: question_embeddings_pos  [2B, 1024] f32
//   1: question_embeddings_neg  [23B, 1024] f32
//   2: pos_image_embeddings     [2B, 1024] f32
//   3: neg_image_embeddings     [23B, 1024] f32
//   4: batch_size (int scalar)
// Output: f32 scalar.
// ---------------------------------------------------------------------------
extern "C" void kernel_launch(void* const* d_in, const int* in_sizes, int n_in,
                              void* d_out, int out_size) {
    const float* q_pos = (const float*)d_in[0];
    const float* q_neg = (const float*)d_in[1];
    const float* i_pos = (const float*)d_in[2];
    const float* i_neg = (const float*)d_in[3];
    float* out = (float*)d_out;

    const int D = 1024;
    const int B = in_sizes[0] / (2 * D);
    const int pos_rows = 2 * B;
    const int total_rows = 25 * B;

    const int WPB = 8;  // 256 threads / block
    contrastive_kernel<<<(total_rows + WPB - 1) / WPB, WPB * 32>>>(
        q_pos, i_pos, q_neg, i_neg, out, pos_rows, total_rows, B);
}